// round 1
// baseline (speedup 1.0000x reference)
#include <cuda_runtime.h>

#define DIM    256
#define NEMB   8192
#define NROW   16384
#define TM     128
#define TN     128
#define KC     16
#define ASTR   136          // A smem row stride in floats (padded, 16B-aligned rows)
#define DECAYF 0.99f
#define OMDF   0.01f
#define EPSF   1e-5f

// ---- scratch (device globals: no allocations allowed) ----
__device__ float g_enorm[NEMB];
__device__ float g_embT[NEMB * DIM];    // [j][d] transposed codebook for coalesced gather
__device__ float g_esum[NEMB * DIM];    // [j][d] segment sums
__device__ int   g_argmin[NROW];
__device__ float g_n;

// ---------------- prep: transpose codebook + zero esum ----------------
__global__ void k_prep(const float* __restrict__ emb) {
    int i = blockIdx.x * blockDim.x + threadIdx.x;
    if (i < NEMB * DIM) {
        int d = i >> 13;          // i / 8192
        int j = i & (NEMB - 1);
        g_embT[j * DIM + d] = emb[i];
        g_esum[i] = 0.0f;
    }
}

// ---------------- code norms + init new_cluster_size + zero diff ----------------
__global__ void k_enorm(const float* __restrict__ emb, const float* __restrict__ cs,
                        float* __restrict__ o_cs, float* __restrict__ o_diff) {
    int j = blockIdx.x * blockDim.x + threadIdx.x;
    if (j < NEMB) {
        float s = 0.0f;
#pragma unroll 8
        for (int d = 0; d < DIM; ++d) {
            float v = emb[d * NEMB + j];
            s = fmaf(v, v, s);
        }
        g_enorm[j] = s;
        o_cs[j] = DECAYF * cs[j];
        if (j == 0) *o_diff = 0.0f;
    }
}

// ---------------- main: fp32x2 GEMM + running argmin ----------------
// block: 256 threads (16x16), 128 rows, loops 64 chunks of 128 codes, K=256.
__global__ __launch_bounds__(256, 1)
void k_argmin(const float* __restrict__ z, const float* __restrict__ emb,
              float* __restrict__ o_ind) {
    extern __shared__ float sm[];
    float* As = sm;                              // 256*136 floats
    float* Bs = sm + DIM * ASTR;                 // 2 * 16 * 256 floats (dup-packed)
    float* En = Bs + 2 * KC * 2 * TN;            // 8192 floats

    const int tid = threadIdx.x;
    const int tx = tid & 15;
    const int ty = tid >> 4;
    const int row0 = blockIdx.x * TM;

    // Fill A transposed: As[d][m] = z[row0+m][d]
    for (int i = tid * 4; i < TM * DIM; i += 256 * 4) {
        int m = i >> 8;
        int d = i & 255;
        float4 v = *reinterpret_cast<const float4*>(z + (size_t)(row0 + m) * DIM + d);
        As[(d + 0) * ASTR + m] = v.x;
        As[(d + 1) * ASTR + m] = v.y;
        As[(d + 2) * ASTR + m] = v.z;
        As[(d + 3) * ASTR + m] = v.w;
    }
    for (int i = tid; i < NEMB; i += 256) En[i] = g_enorm[i];
    __syncthreads();

    const unsigned sbase = (unsigned)__cvta_generic_to_shared(sm);
    const unsigned boff0 = (unsigned)(DIM * ASTR) * 4u;   // byte offset of Bs

    float bestv[8];
    int   besti[8];
#pragma unroll
    for (int r = 0; r < 8; ++r) { bestv[r] = 3.4e38f; besti[r] = 0; }

    float rb[8];

    for (int chunk = 0; chunk < NEMB / TN; ++chunk) {
        const int cbase = chunk * TN;

        unsigned long long acc[4][8];
#pragma unroll
        for (int rp = 0; rp < 4; ++rp)
#pragma unroll
            for (int c = 0; c < 8; ++c) acc[rp][c] = 0ULL;

        // ---- slice prefetch helpers ----
        auto load_slice = [&](int s) {
#pragma unroll
            for (int r = 0; r < 8; ++r) {
                int e = tid + (r << 8);
                int kc = e >> 7;
                int n = e & 127;
                rb[r] = __ldg(&emb[(size_t)(s * KC + kc) * NEMB + cbase + n]);
            }
        };
        auto store_slice = [&](int buf) {
#pragma unroll
            for (int r = 0; r < 8; ++r) {
                int e = tid + (r << 8);
                int kc = e >> 7;
                int n = e & 127;
                float v = rb[r];
                *reinterpret_cast<float2*>(&Bs[buf * (KC * 2 * TN) + kc * (2 * TN) + 2 * n]) =
                    make_float2(v, v);
            }
        };

        load_slice(0);
        store_slice(0);
        load_slice(1);
        __syncthreads();

        int buf = 0;
        for (int s = 0; s < 16; ++s) {
            // ---- compute KC k-steps from As / Bs[buf] ----
#pragma unroll
            for (int kc = 0; kc < KC; ++kc) {
                const int k = s * KC + kc;
                unsigned aaddr = sbase + ((unsigned)(k * ASTR + ty * 8) << 2);
                unsigned long long a0, a1, a2, a3;
                asm volatile("ld.shared.v2.b64 {%0,%1},[%2];"
                             : "=l"(a0), "=l"(a1) : "r"(aaddr));
                asm volatile("ld.shared.v2.b64 {%0,%1},[%2];"
                             : "=l"(a2), "=l"(a3) : "r"(aaddr + 16));
                unsigned baddr = sbase + boff0 +
                    ((unsigned)(buf * (KC * 2 * TN) + kc * (2 * TN) + tx * 16) << 2);
                unsigned long long b[8];
                asm volatile("ld.shared.v2.b64 {%0,%1},[%2];"
                             : "=l"(b[0]), "=l"(b[1]) : "r"(baddr));
                asm volatile("ld.shared.v2.b64 {%0,%1},[%2];"
                             : "=l"(b[2]), "=l"(b[3]) : "r"(baddr + 16));
                asm volatile("ld.shared.v2.b64 {%0,%1},[%2];"
                             : "=l"(b[4]), "=l"(b[5]) : "r"(baddr + 32));
                asm volatile("ld.shared.v2.b64 {%0,%1},[%2];"
                             : "=l"(b[6]), "=l"(b[7]) : "r"(baddr + 48));
#pragma unroll
                for (int c = 0; c < 8; ++c) {
                    asm volatile("fma.rn.f32x2 %0,%1,%2,%0;" : "+l"(acc[0][c]) : "l"(a0), "l"(b[c]));
                    asm volatile("fma.rn.f32x2 %0,%1,%2,%0;" : "+l"(acc[1][c]) : "l"(a1), "l"(b[c]));
                    asm volatile("fma.rn.f32x2 %0,%1,%2,%0;" : "+l"(acc[2][c]) : "l"(a2), "l"(b[c]));
                    asm volatile("fma.rn.f32x2 %0,%1,%2,%0;" : "+l"(acc[3][c]) : "l"(a3), "l"(b[c]));
                }
            }
            if (s < 15) {
                store_slice(buf ^ 1);
                if (s < 14) load_slice(s + 2);
            }
            __syncthreads();
            buf ^= 1;
        }

        // ---- fold chunk into running argmin (codes ascending -> first-min tie-break) ----
#pragma unroll
        for (int c = 0; c < 8; ++c) {
            const int code = cbase + tx * 8 + c;
            const float en = En[code];
#pragma unroll
            for (int rp = 0; rp < 4; ++rp) {
                unsigned long long v = acc[rp][c];
                float lo = __uint_as_float((unsigned)v);
                float hi = __uint_as_float((unsigned)(v >> 32));
                float slo = fmaf(-2.0f, lo, en);
                float shi = fmaf(-2.0f, hi, en);
                int r0 = rp * 2, r1 = rp * 2 + 1;
                if (slo < bestv[r0]) { bestv[r0] = slo; besti[r0] = code; }
                if (shi < bestv[r1]) { bestv[r1] = shi; besti[r1] = code; }
            }
        }
    }

    // ---- cross-thread (tx) reduction per row ----
    __syncthreads();
    float* redv = Bs;                  // reuse B buffers (16 KB)
    int*   redi = (int*)(Bs + 2048);
#pragma unroll
    for (int r = 0; r < 8; ++r) {
        int rl = ty * 8 + r;
        redv[rl * 16 + tx] = bestv[r];
        redi[rl * 16 + tx] = besti[r];
    }
    __syncthreads();
    if (tid < TM) {
        float bv = redv[tid * 16];
        int bi = redi[tid * 16];
#pragma unroll
        for (int t = 1; t < 16; ++t) {
            float v = redv[tid * 16 + t];
            int ix = redi[tid * 16 + t];
            if (v < bv || (v == bv && ix < bi)) { bv = v; bi = ix; }
        }
        g_argmin[row0 + tid] = bi;
        o_ind[row0 + tid] = (float)bi;
    }
}

// ---------------- gather quantize + diff + segment-sum scatter ----------------
__global__ void k_scatter(const float* __restrict__ z, float* __restrict__ o_quant,
                          float* __restrict__ o_diff, float* __restrict__ o_cs) {
    int gw = (blockIdx.x * blockDim.x + threadIdx.x) >> 5;   // one warp per row
    int lane = threadIdx.x & 31;
    if (gw >= NROW) return;
    int j = g_argmin[gw];
    const float* et = &g_embT[(size_t)j * DIM];
    const float* zr = &z[(size_t)gw * DIM];
    float* qr = &o_quant[(size_t)gw * DIM];
    float* es = &g_esum[(size_t)j * DIM];
    float s = 0.0f;
#pragma unroll
    for (int it = 0; it < 8; ++it) {
        int d = it * 32 + lane;
        float q = et[d];
        float zv = zr[d];
        float dq = q - zv;
        qr[d] = zv + dq;                 // z + stop_grad(q - z)
        s = fmaf(dq, dq, s);
        atomicAdd(&es[d], zv);
    }
#pragma unroll
    for (int o = 16; o; o >>= 1) s += __shfl_xor_sync(0xffffffffu, s, o);
    if (lane == 0) {
        atomicAdd(o_diff, s * (1.0f / (float)(NROW * DIM)));
        atomicAdd(&o_cs[j], OMDF);
    }
}

// ---------------- n = sum(new_cluster_size) ----------------
__global__ void k_sumn(const float* __restrict__ o_cs) {
    __shared__ float sh[256];
    float s = 0.0f;
    for (int i = threadIdx.x; i < NEMB; i += 256) s += o_cs[i];
    sh[threadIdx.x] = s;
    __syncthreads();
    for (int o = 128; o; o >>= 1) {
        if (threadIdx.x < o) sh[threadIdx.x] += sh[threadIdx.x + o];
        __syncthreads();
    }
    if (threadIdx.x == 0) g_n = sh[0];
}

// ---------------- new_embedding_avg + new_embedding ----------------
__global__ void k_final(const float* __restrict__ avg, const float* __restrict__ o_cs,
                        float* __restrict__ o_emb, float* __restrict__ o_avg) {
    int i = blockIdx.x * blockDim.x + threadIdx.x;
    if (i >= NEMB * DIM) return;
    int d = i >> 13;
    int j = i & (NEMB - 1);
    float na = fmaf(OMDF, g_esum[j * DIM + d], DECAYF * avg[i]);
    o_avg[i] = na;
    float n = g_n;
    float cs = o_cs[j];
    float smth = (cs + EPSF) / (n + (float)NEMB * EPSF) * n;
    o_emb[i] = na / smth;
}

extern "C" void kernel_launch(void* const* d_in, const int* in_sizes, int n_in,
                              void* d_out, int out_size) {
    (void)in_sizes; (void)n_in; (void)out_size;
    const float* z   = (const float*)d_in[0];
    const float* emb = (const float*)d_in[1];
    const float* cs  = (const float*)d_in[2];
    const float* avg = (const float*)d_in[3];

    float* out     = (float*)d_out;
    float* o_quant = out;                 // 16*32*32*256 = 4194304
    float* o_diff  = out + 4194304;       // 1
    float* o_ind   = out + 4194305;       // 16384
    float* o_emb   = out + 4210689;       // 2097152
    float* o_cs    = out + 6307841;       // 8192
    float* o_avg   = out + 6316033;       // 2097152

    const int SMEM = (DIM * ASTR + 2 * KC * 2 * TN + NEMB) * 4;  // 204800 B
    cudaFuncSetAttribute(k_argmin, cudaFuncAttributeMaxDynamicSharedMemorySize, SMEM);

    k_prep  <<<(NEMB * DIM + 255) / 256, 256>>>(emb);
    k_enorm <<<(NEMB + 255) / 256, 256>>>(emb, cs, o_cs, o_diff);
    k_argmin<<<NROW / TM, 256, SMEM>>>(z, emb, o_ind);
    k_scatter<<<(NROW * 32) / 256, 256>>>(z, o_quant, o_diff, o_cs);
    k_sumn  <<<1, 256>>>(o_cs);
    k_final <<<(NEMB * DIM + 255) / 256, 256>>>(avg, o_cs, o_emb, o_avg);
}

// round 3
// speedup vs baseline: 4.8388x; 4.8388x over previous
#include <cuda_runtime.h>
#include <cuda_bf16.h>
#include <cstdint>

#define DIM    256
#define NEMB   8192
#define NROW   16384
#define DECAYF 0.99f
#define OMDF   0.01f
#define EPSF   1e-5f

// A: 2 regions (hi,lo) x 128 rows x 512B (256 bf16), padded stride 528B
#define AST    528
#define AREG   (128 * AST)          // 67584
#define BST    144                  // B slice row: 64 bf16 = 128B + 16 pad
#define BBUF   (128 * BST)          // 18432
#define SM_A   0
#define SM_B   (2 * AREG)           // 135168
#define SM_EN  (SM_B + 2 * BBUF)    // 172032
#define SMEM_SZ (SM_EN + NEMB * 4)  // 204800

// ---- scratch (device globals: no allocations allowed) ----
__device__ float g_enorm[NEMB];
__device__ float g_embT[NEMB * DIM];          // [j][d] for coalesced gather
__device__ float g_esum[NEMB * DIM];          // [j][d] segment sums
__device__ int   g_argmin[NROW];
__device__ float g_n;
__device__ __nv_bfloat16 g_zs2[(size_t)NROW * 512];   // [m][hi(256)|lo(256)]
__device__ __nv_bfloat16 g_es2[(size_t)NEMB * 512];   // [j][hi(256)|lo(256)]

// ================= helpers =================
__device__ __forceinline__ uint32_t smem_u32(const void* p) {
    uint32_t a;
    asm("{ .reg .u64 t; cvta.to.shared.u64 t, %1; cvt.u32.u64 %0, t; }" : "=r"(a) : "l"(p));
    return a;
}
__device__ __forceinline__ void cpa16(uint32_t dst, const void* src) {
    asm volatile("cp.async.cg.shared.global [%0], [%1], 16;" :: "r"(dst), "l"(src));
}
__device__ __forceinline__ void ldm4(uint32_t (&r)[4], uint32_t addr) {
    asm volatile("ldmatrix.sync.aligned.m8n8.x4.shared.b16 {%0,%1,%2,%3}, [%4];"
                 : "=r"(r[0]), "=r"(r[1]), "=r"(r[2]), "=r"(r[3]) : "r"(addr));
}
__device__ __forceinline__ void mma16816(float (&d)[4], const uint32_t (&a)[4],
                                         uint32_t b0, uint32_t b1) {
    asm volatile(
        "mma.sync.aligned.m16n8k16.row.col.f32.bf16.bf16.f32 "
        "{%0,%1,%2,%3},{%4,%5,%6,%7},{%8,%9},{%0,%1,%2,%3};"
        : "+f"(d[0]), "+f"(d[1]), "+f"(d[2]), "+f"(d[3])
        : "r"(a[0]), "r"(a[1]), "r"(a[2]), "r"(a[3]), "r"(b0), "r"(b1));
}

// ================= prep: z -> [hi|lo] bf16 =================
__global__ void k_prep_z(const float* __restrict__ z) {
    int i = blockIdx.x * blockDim.x + threadIdx.x;
    if (i >= NROW * DIM) return;
    int m = i >> 8, d = i & 255;
    float x = z[i];
    __nv_bfloat16 hi = __float2bfloat16(x);
    __nv_bfloat16 lo = __float2bfloat16(x - __bfloat162float(hi));
    size_t b = ((size_t)m << 9) + d;
    g_zs2[b] = hi; g_zs2[b + 256] = lo;
}

// ================= prep: emb -> [hi|lo] bf16 + embT + esum=0 (tiled transpose) ====
__global__ void k_prep_e(const float* __restrict__ emb) {
    __shared__ float t[32][33];
    int j0 = blockIdx.x * 32, d0 = blockIdx.y * 32;
    for (int r = threadIdx.y; r < 32; r += 8)
        t[r][threadIdx.x] = emb[(size_t)(d0 + r) * NEMB + j0 + threadIdx.x];
    __syncthreads();
    for (int r = threadIdx.y; r < 32; r += 8) {
        int j = j0 + r, d = d0 + threadIdx.x;
        float x = t[threadIdx.x][r];
        __nv_bfloat16 hi = __float2bfloat16(x);
        __nv_bfloat16 lo = __float2bfloat16(x - __bfloat162float(hi));
        size_t b = ((size_t)j << 9) + d;
        g_es2[b] = hi; g_es2[b + 256] = lo;
        g_embT[j * DIM + d] = x;
        g_esum[j * DIM + d] = 0.0f;
    }
}

// ================= code norms + init cs + zero diff =================
__global__ void k_enorm(const float* __restrict__ emb, const float* __restrict__ cs,
                        float* __restrict__ o_cs, float* __restrict__ o_diff) {
    int j = blockIdx.x * blockDim.x + threadIdx.x;
    if (j < NEMB) {
        float s = 0.0f;
#pragma unroll 8
        for (int d = 0; d < DIM; ++d) {
            float v = emb[(size_t)d * NEMB + j];
            s = fmaf(v, v, s);
        }
        g_enorm[j] = s;
        o_cs[j] = DECAYF * cs[j];
        if (j == 0) *o_diff = 0.0f;
    }
}

// ================= main: HMMA bf16 split GEMM + argmin =================
__device__ __forceinline__ void load_B(int ch, int s, int buf, int tid, uint32_t sb) {
    const int n0 = ch << 7;
    const int scol = s << 6;            // s 0-3: hi cols, s 4-7: lo cols
    const char* ea = (const char*)g_es2;
#pragma unroll
    for (int r = 0; r < 4; ++r) {
        int i = tid + (r << 8);
        int c = i & 7, row = i >> 3;
        cpa16(sb + SM_B + buf * BBUF + row * BST + c * 16,
              ea + (((size_t)(n0 + row) << 9) + scol) * 2 + c * 16);
    }
}

__global__ __launch_bounds__(256, 1)
void k_argmin_mma(float* __restrict__ o_ind) {
    extern __shared__ char smm[];
    uint32_t sb = smem_u32(smm);
    const int tid = threadIdx.x;
    const int lane = tid & 31;
    const int warp = tid >> 5;
    const int warpM = warp >> 1;        // 0..3 (32 rows each)
    const int warpN = warp & 1;         // 0..1 (64 codes each)
    const int m0 = blockIdx.x * 128;

    // per-lane ldmatrix offsets
    const int q = lane >> 3, rq = lane & 7;
    const int lrow = (q & 1) * 8 + rq;
    const int lbyte = (q >> 1) * 16;
    const uint32_t a_lane = (uint32_t)lrow * AST + lbyte;
    const uint32_t b_lane = (uint32_t)lrow * BST + lbyte;

    // A persistent load (both regions), en, and first B slice — one cp.async group
    const char* za = (const char*)g_zs2;
    for (int i = tid; i < 8192; i += 256) {
        int c = i & 31, row = (i >> 5) & 127, r = i >> 12;
        cpa16(sb + SM_A + r * AREG + row * AST + c * 16,
              za + (((size_t)(m0 + row) << 9) + (r << 8)) * 2 + c * 16);
    }
    load_B(0, 0, 0, tid, sb);
    asm volatile("cp.async.commit_group;" ::: "memory");

    float* en_s = (float*)(smm + SM_EN);
    for (int i = tid; i < NEMB; i += 256) en_s[i] = g_enorm[i];

    float bestv[4];
    int   besti[4];
#pragma unroll
    for (int sl = 0; sl < 4; ++sl) { bestv[sl] = 3.4e38f; besti[sl] = 0; }

    const int lq = lane >> 2;
    const int ln = (lane & 3) * 2;

    int buf = 0;
    for (int ch = 0; ch < 64; ++ch) {
        const int n0 = ch << 7;
        float acc[2][8][4];
#pragma unroll
        for (int mt = 0; mt < 2; ++mt)
#pragma unroll
            for (int nt = 0; nt < 8; ++nt)
#pragma unroll
                for (int x = 0; x < 4; ++x) acc[mt][nt][x] = 0.0f;

        for (int s = 0; s < 8; ++s) {
            const int gs = ch * 8 + s;
            if (gs + 1 < 64 * 8) {
                load_B((gs + 1) >> 3, (gs + 1) & 7, buf ^ 1, tid, sb);
                asm volatile("cp.async.commit_group;" ::: "memory");
                asm volatile("cp.async.wait_group 1;" ::: "memory");
            } else {
                asm volatile("cp.async.wait_group 0;" ::: "memory");
            }
            __syncthreads();

            const uint32_t Bb = sb + SM_B + buf * BBUF + (warpN * 64) * BST + b_lane;
            const int koffA = (s & 3) * 64;
#pragma unroll
            for (int r = 0; r < 2; ++r) {
                const uint32_t Ab = sb + SM_A + r * AREG + (warpM * 32) * AST +
                                    koffA * 2 + a_lane;
#pragma unroll
                for (int kk = 0; kk < 4; ++kk) {
                    uint32_t a0[4], a1[4];
                    ldm4(a0, Ab + kk * 32);
                    ldm4(a1, Ab + 16 * AST + kk * 32);
                    uint32_t b[4][4];
#pragma unroll
                    for (int g = 0; g < 4; ++g)
                        ldm4(b[g], Bb + g * 16 * BST + kk * 32);
#pragma unroll
                    for (int nt = 0; nt < 8; ++nt) {
                        uint32_t b0 = b[nt >> 1][nt & 1];
                        uint32_t b1 = b[nt >> 1][(nt & 1) + 2];
                        mma16816(acc[0][nt], a0, b0, b1);
                        mma16816(acc[1][nt], a1, b0, b1);
                    }
                }
            }
            __syncthreads();
            buf ^= 1;
        }

        // fold chunk into running argmin (codes ascending -> first-min ties)
#pragma unroll
        for (int nt = 0; nt < 8; ++nt) {
            const int codeb = n0 + warpN * 64 + nt * 8 + ln;
#pragma unroll
            for (int jj = 0; jj < 2; ++jj) {
                const int code = codeb + jj;
                const float en = en_s[code];
                float d0 = fmaf(-2.0f, acc[0][nt][jj], en);
                if (d0 < bestv[0]) { bestv[0] = d0; besti[0] = code; }
                float d1 = fmaf(-2.0f, acc[0][nt][2 + jj], en);
                if (d1 < bestv[1]) { bestv[1] = d1; besti[1] = code; }
                float d2 = fmaf(-2.0f, acc[1][nt][jj], en);
                if (d2 < bestv[2]) { bestv[2] = d2; besti[2] = code; }
                float d3 = fmaf(-2.0f, acc[1][nt][2 + jj], en);
                if (d3 < bestv[3]) { bestv[3] = d3; besti[3] = code; }
            }
        }
    }

    // final cross-thread reduction: 8 contributors per row
    __syncthreads();
    float* redv = (float*)(smm + SM_B);
    int*   redi = (int*)(smm + SM_B + 4096);
    const int contrib = warpN * 4 + (lane & 3);
#pragma unroll
    for (int sl = 0; sl < 4; ++sl) {
        // sl = mt*2 + pair ; row = warpM*32 + mt*16 + pair*8 + lq
        int row = warpM * 32 + (sl >> 1) * 16 + (sl & 1) * 8 + lq;
        redv[row * 8 + contrib] = bestv[sl];
        redi[row * 8 + contrib] = besti[sl];
    }
    __syncthreads();
    if (tid < 128) {
        float bv = redv[tid * 8];
        int bi = redi[tid * 8];
#pragma unroll
        for (int t = 1; t < 8; ++t) {
            float v = redv[tid * 8 + t];
            int ix = redi[tid * 8 + t];
            if (v < bv || (v == bv && ix < bi)) { bv = v; bi = ix; }
        }
        g_argmin[m0 + tid] = bi;
        o_ind[m0 + tid] = (float)bi;
    }
}

// ================= gather quantize + diff + segment-sum scatter =================
__global__ void k_scatter(const float* __restrict__ z, float* __restrict__ o_quant,
                          float* __restrict__ o_diff, float* __restrict__ o_cs) {
    int gw = (blockIdx.x * blockDim.x + threadIdx.x) >> 5;
    int lane = threadIdx.x & 31;
    if (gw >= NROW) return;
    int j = g_argmin[gw];
    const float* et = &g_embT[(size_t)j * DIM];
    const float* zr = &z[(size_t)gw * DIM];
    float* qr = &o_quant[(size_t)gw * DIM];
    float* es = &g_esum[(size_t)j * DIM];
    float s = 0.0f;
#pragma unroll
    for (int it = 0; it < 8; ++it) {
        int d = it * 32 + lane;
        float qv = et[d];
        float zv = zr[d];
        float dq = qv - zv;
        qr[d] = zv + dq;
        s = fmaf(dq, dq, s);
        atomicAdd(&es[d], zv);
    }
#pragma unroll
    for (int o = 16; o; o >>= 1) s += __shfl_xor_sync(0xffffffffu, s, o);
    if (lane == 0) {
        atomicAdd(o_diff, s * (1.0f / (float)(NROW * DIM)));
        atomicAdd(&o_cs[j], OMDF);
    }
}

// ================= n = sum(new_cluster_size) =================
__global__ void k_sumn(const float* __restrict__ o_cs) {
    __shared__ float sh[256];
    float s = 0.0f;
    for (int i = threadIdx.x; i < NEMB; i += 256) s += o_cs[i];
    sh[threadIdx.x] = s;
    __syncthreads();
    for (int o = 128; o; o >>= 1) {
        if (threadIdx.x < o) sh[threadIdx.x] += sh[threadIdx.x + o];
        __syncthreads();
    }
    if (threadIdx.x == 0) g_n = sh[0];
}

// ================= new_embedding_avg + new_embedding =================
__global__ void k_final(const float* __restrict__ avg, const float* __restrict__ o_cs,
                        float* __restrict__ o_emb, float* __restrict__ o_avg) {
    int i = blockIdx.x * blockDim.x + threadIdx.x;
    if (i >= NEMB * DIM) return;
    int d = i >> 13;
    int j = i & (NEMB - 1);
    float na = fmaf(OMDF, g_esum[j * DIM + d], DECAYF * avg[i]);
    o_avg[i] = na;
    float n = g_n;
    float cs = o_cs[j];
    float smth = (cs + EPSF) / (n + (float)NEMB * EPSF) * n;
    o_emb[i] = na / smth;
}

extern "C" void kernel_launch(void* const* d_in, const int* in_sizes, int n_in,
                              void* d_out, int out_size) {
    (void)in_sizes; (void)n_in; (void)out_size;
    const float* z   = (const float*)d_in[0];
    const float* emb = (const float*)d_in[1];
    const float* cs  = (const float*)d_in[2];
    const float* avg = (const float*)d_in[3];

    float* out     = (float*)d_out;
    float* o_quant = out;                 // 4194304
    float* o_diff  = out + 4194304;       // 1
    float* o_ind   = out + 4194305;       // 16384
    float* o_emb   = out + 4210689;       // 2097152
    float* o_cs    = out + 6307841;       // 8192
    float* o_avg   = out + 6316033;       // 2097152

    cudaFuncSetAttribute(k_argmin_mma, cudaFuncAttributeMaxDynamicSharedMemorySize, SMEM_SZ);

    k_prep_z<<<(NROW * DIM + 255) / 256, 256>>>(z);
    {
        dim3 g(NEMB / 32, DIM / 32), b(32, 8);
        k_prep_e<<<g, b>>>(emb);
    }
    k_enorm<<<(NEMB + 255) / 256, 256>>>(emb, cs, o_cs, o_diff);
    k_argmin_mma<<<NROW / 128, 256, SMEM_SZ>>>(o_ind);
    k_scatter<<<(NROW * 32) / 256, 256>>>(z, o_quant, o_diff, o_cs);
    k_sumn<<<1, 256>>>(o_cs);
    k_final<<<(NEMB * DIM + 255) / 256, 256>>>(avg, o_cs, o_emb, o_avg);
}

// round 4
// speedup vs baseline: 5.5861x; 1.1544x over previous
#include <cuda_runtime.h>
#include <cuda_fp16.h>
#include <cstdint>

#define DIM    256
#define NEMB   8192
#define NROW   16384
#define DECAYF 0.99f
#define OMDF   0.01f
#define EPSF   1e-5f

// A: 2 regions (hi,lo) x 128 rows x 512B (256 fp16), padded stride 528B
#define AST    528
#define AREG   (128 * AST)          // 67584
#define BST    144                  // B slice row: 64 fp16 = 128B + 16 pad
#define BBUF   (128 * BST)          // 18432
#define SM_A   0
#define SM_B   (2 * AREG)           // 135168
#define SMEM_SZ (SM_B + 3 * BBUF)   // 190464
#define NSTG   512                  // 64 chunks x 8 stages

// ---- scratch (device globals: no allocations allowed) ----
__device__ float g_enorm[NEMB];
__device__ float g_embT[NEMB * DIM];          // [j][d] for coalesced gather
__device__ float g_esum[NEMB * DIM];          // [j][d] segment sums
__device__ int   g_argmin[NROW];
__device__ float g_n;
__device__ __half g_zs2[(size_t)NROW * 512];  // [m][hi(256)|lo(256)]
__device__ __half g_es2[(size_t)NEMB * 512];  // [j][hi(256)|lo(256)]

// ================= helpers =================
__device__ __forceinline__ uint32_t smem_u32(const void* p) {
    uint32_t a;
    asm("{ .reg .u64 t; cvta.to.shared.u64 t, %1; cvt.u32.u64 %0, t; }" : "=r"(a) : "l"(p));
    return a;
}
__device__ __forceinline__ void cpa16(uint32_t dst, const void* src) {
    asm volatile("cp.async.cg.shared.global [%0], [%1], 16;" :: "r"(dst), "l"(src));
}
__device__ __forceinline__ void ldm4(uint32_t (&r)[4], uint32_t addr) {
    asm volatile("ldmatrix.sync.aligned.m8n8.x4.shared.b16 {%0,%1,%2,%3}, [%4];"
                 : "=r"(r[0]), "=r"(r[1]), "=r"(r[2]), "=r"(r[3]) : "r"(addr));
}
__device__ __forceinline__ void mma16816(float (&d)[4], const uint32_t (&a)[4],
                                         uint32_t b0, uint32_t b1) {
    asm volatile(
        "mma.sync.aligned.m16n8k16.row.col.f32.f16.f16.f32 "
        "{%0,%1,%2,%3},{%4,%5,%6,%7},{%8,%9},{%0,%1,%2,%3};"
        : "+f"(d[0]), "+f"(d[1]), "+f"(d[2]), "+f"(d[3])
        : "r"(a[0]), "r"(a[1]), "r"(a[2]), "r"(a[3]), "r"(b0), "r"(b1));
}

// ================= prep: z -> [hi|lo] fp16 =================
__global__ void k_prep_z(const float* __restrict__ z) {
    int i = blockIdx.x * blockDim.x + threadIdx.x;
    if (i >= NROW * DIM) return;
    int m = i >> 8, d = i & 255;
    float x = z[i];
    __half hi = __float2half(x);
    __half lo = __float2half(x - __half2float(hi));
    size_t b = ((size_t)m << 9) + d;
    g_zs2[b] = hi; g_zs2[b + 256] = lo;
}

// ================= prep: emb -> [hi|lo] fp16 + embT + esum=0 (tiled transpose) ====
__global__ void k_prep_e(const float* __restrict__ emb) {
    __shared__ float t[32][33];
    int j0 = blockIdx.x * 32, d0 = blockIdx.y * 32;
    for (int r = threadIdx.y; r < 32; r += 8)
        t[r][threadIdx.x] = emb[(size_t)(d0 + r) * NEMB + j0 + threadIdx.x];
    __syncthreads();
    for (int r = threadIdx.y; r < 32; r += 8) {
        int j = j0 + r, d = d0 + threadIdx.x;
        float x = t[threadIdx.x][r];
        __half hi = __float2half(x);
        __half lo = __float2half(x - __half2float(hi));
        size_t b = ((size_t)j << 9) + d;
        g_es2[b] = hi; g_es2[b + 256] = lo;
        g_embT[j * DIM + d] = x;
        g_esum[j * DIM + d] = 0.0f;
    }
}

// ================= code norms + init cs + zero diff =================
__global__ void k_enorm(const float* __restrict__ emb, const float* __restrict__ cs,
                        float* __restrict__ o_cs, float* __restrict__ o_diff) {
    int j = blockIdx.x * blockDim.x + threadIdx.x;
    if (j < NEMB) {
        float s = 0.0f;
#pragma unroll 8
        for (int d = 0; d < DIM; ++d) {
            float v = emb[(size_t)d * NEMB + j];
            s = fmaf(v, v, s);
        }
        g_enorm[j] = s;
        o_cs[j] = DECAYF * cs[j];
        if (j == 0) *o_diff = 0.0f;
    }
}

// ================= main: HMMA fp16 3-term GEMM + argmin =================
__device__ __forceinline__ void load_B(int t, int slot, int tid, uint32_t sb) {
    const int ch = t >> 3;
    const int s = t & 7;
    const int n0 = ch << 7;
    const int scol = s << 6;            // 64 fp16 per stage; s<4 hi, s>=4 lo
    const char* ea = (const char*)g_es2;
#pragma unroll
    for (int r = 0; r < 4; ++r) {
        int i = tid + (r << 8);
        int c = i & 7, row = i >> 3;
        cpa16(sb + SM_B + slot * BBUF + row * BST + c * 16,
              ea + (((size_t)(n0 + row) << 9) + scol) * 2 + c * 16);
    }
}

__global__ __launch_bounds__(256, 1)
void k_argmin_mma(float* __restrict__ o_ind) {
    extern __shared__ char smm[];
    uint32_t sb = smem_u32(smm);
    const int tid = threadIdx.x;
    const int lane = tid & 31;
    const int warp = tid >> 5;
    const int warpM = warp >> 1;        // 0..3 (32 rows each)
    const int warpN = warp & 1;         // 0..1 (64 codes each)
    const int m0 = blockIdx.x * 128;

    // per-lane ldmatrix offsets
    const int q = lane >> 3, rq = lane & 7;
    const int lrow = (q & 1) * 8 + rq;
    const int lbyte = (q >> 1) * 16;
    const uint32_t a_lane = (uint32_t)lrow * AST + lbyte;
    const uint32_t b_lane = (uint32_t)lrow * BST + lbyte;

    // prologue: A (both regions) + stage 0 -> group0; stage 1 -> group1
    const char* za = (const char*)g_zs2;
#pragma unroll
    for (int r = 0; r < 32; ++r) {
        int i = tid + (r << 8);
        int c = i & 31, row = (i >> 5) & 127, reg = i >> 12;
        cpa16(sb + SM_A + reg * AREG + row * AST + c * 16,
              za + (((size_t)(m0 + row) << 9) + (reg << 8)) * 2 + c * 16);
    }
    load_B(0, 0, tid, sb);
    asm volatile("cp.async.commit_group;" ::: "memory");
    load_B(1, 1, tid, sb);
    asm volatile("cp.async.commit_group;" ::: "memory");

    float bestv[4];
    int   besti[4];
#pragma unroll
    for (int sl = 0; sl < 4; ++sl) { bestv[sl] = 3.4e38f; besti[sl] = 0; }

    const int lq = lane >> 2;
    const int ln = (lane & 3) * 2;

    float acc[2][8][4];
    int cur = 0, nxt = 2;

    for (int t = 0; t < NSTG; ++t) {
        const int s = t & 7;
        if (s == 0) {
#pragma unroll
            for (int mt = 0; mt < 2; ++mt)
#pragma unroll
                for (int nt = 0; nt < 8; ++nt)
#pragma unroll
                    for (int x = 0; x < 4; ++x) acc[mt][nt][x] = 0.0f;
        }

        if (t == NSTG - 1) {
            asm volatile("cp.async.wait_group 0;" ::: "memory");
        } else {
            asm volatile("cp.async.wait_group 1;" ::: "memory");
        }
        __syncthreads();     // stage t ready for all; mma(t-1) done by all

        if (t + 2 < NSTG) {
            load_B(t + 2, nxt, tid, sb);
            asm volatile("cp.async.commit_group;" ::: "memory");
        }

        const uint32_t Bb = sb + SM_B + cur * BBUF + (warpN * 64) * BST + b_lane;
        const uint32_t Ab0 = sb + SM_A + (warpM * 32) * AST + (s & 3) * 128 + a_lane;
        const bool two = (s < 4);
#pragma unroll
        for (int kk = 0; kk < 4; ++kk) {
            uint32_t b[4][4];
#pragma unroll
            for (int g = 0; g < 4; ++g)
                ldm4(b[g], Bb + g * 16 * BST + kk * 32);
            uint32_t a0[4], a1[4];
            ldm4(a0, Ab0 + kk * 32);
            ldm4(a1, Ab0 + 16 * AST + kk * 32);
#pragma unroll
            for (int nt = 0; nt < 8; ++nt) {
                uint32_t b0 = b[nt >> 1][nt & 1];
                uint32_t b1 = b[nt >> 1][(nt & 1) + 2];
                mma16816(acc[0][nt], a0, b0, b1);
                mma16816(acc[1][nt], a1, b0, b1);
            }
            if (two) {   // B-hi also pairs with A-lo region
                ldm4(a0, Ab0 + AREG + kk * 32);
                ldm4(a1, Ab0 + AREG + 16 * AST + kk * 32);
#pragma unroll
                for (int nt = 0; nt < 8; ++nt) {
                    uint32_t b0 = b[nt >> 1][nt & 1];
                    uint32_t b1 = b[nt >> 1][(nt & 1) + 2];
                    mma16816(acc[0][nt], a0, b0, b1);
                    mma16816(acc[1][nt], a1, b0, b1);
                }
            }
        }

        if (s == 7) {   // chunk done: fold into running argmin
            const int n0 = (t >> 3) << 7;
#pragma unroll
            for (int nt = 0; nt < 8; ++nt) {
                const int codeb = n0 + warpN * 64 + nt * 8 + ln;
#pragma unroll
                for (int jj = 0; jj < 2; ++jj) {
                    const int code = codeb + jj;
                    const float en = __ldg(&g_enorm[code]);
                    float d0 = fmaf(-2.0f, acc[0][nt][jj], en);
                    if (d0 < bestv[0]) { bestv[0] = d0; besti[0] = code; }
                    float d1 = fmaf(-2.0f, acc[0][nt][2 + jj], en);
                    if (d1 < bestv[1]) { bestv[1] = d1; besti[1] = code; }
                    float d2 = fmaf(-2.0f, acc[1][nt][jj], en);
                    if (d2 < bestv[2]) { bestv[2] = d2; besti[2] = code; }
                    float d3 = fmaf(-2.0f, acc[1][nt][2 + jj], en);
                    if (d3 < bestv[3]) { bestv[3] = d3; besti[3] = code; }
                }
            }
        }

        cur = (cur == 2) ? 0 : cur + 1;
        nxt = (nxt == 2) ? 0 : nxt + 1;
    }

    // final cross-thread reduction: 8 contributors per row
    __syncthreads();
    float* redv = (float*)(smm + SM_B);
    int*   redi = (int*)(smm + SM_B + 4096);
    const int contrib = warpN * 4 + (lane & 3);
#pragma unroll
    for (int sl = 0; sl < 4; ++sl) {
        int row = warpM * 32 + (sl >> 1) * 16 + (sl & 1) * 8 + lq;
        redv[row * 8 + contrib] = bestv[sl];
        redi[row * 8 + contrib] = besti[sl];
    }
    __syncthreads();
    if (tid < 128) {
        float bv = redv[tid * 8];
        int bi = redi[tid * 8];
#pragma unroll
        for (int t = 1; t < 8; ++t) {
            float v = redv[tid * 8 + t];
            int ix = redi[tid * 8 + t];
            if (v < bv || (v == bv && ix < bi)) { bv = v; bi = ix; }
        }
        g_argmin[m0 + tid] = bi;
        o_ind[m0 + tid] = (float)bi;
    }
}

// ================= gather quantize + diff + segment-sum scatter =================
// 2 warps per row (half a row each) for latency hiding
__global__ void k_scatter(const float* __restrict__ z, float* __restrict__ o_quant,
                          float* __restrict__ o_diff, float* __restrict__ o_cs) {
    int gw = (blockIdx.x * blockDim.x + threadIdx.x) >> 5;
    int lane = threadIdx.x & 31;
    int row = gw >> 1;
    int half = gw & 1;
    if (row >= NROW) return;
    int j = g_argmin[row];
    int dbase = half * 128;
    const float* et = &g_embT[(size_t)j * DIM + dbase];
    const float* zr = &z[(size_t)row * DIM + dbase];
    float* qr = &o_quant[(size_t)row * DIM + dbase];
    float* es = &g_esum[(size_t)j * DIM + dbase];
    float s = 0.0f;
#pragma unroll
    for (int it = 0; it < 4; ++it) {
        int d = it * 32 + lane;
        float qv = __ldg(&et[d]);
        float zv = zr[d];
        float dq = qv - zv;
        qr[d] = zv + dq;
        s = fmaf(dq, dq, s);
        atomicAdd(&es[d], zv);
    }
#pragma unroll
    for (int o = 16; o; o >>= 1) s += __shfl_xor_sync(0xffffffffu, s, o);
    if (lane == 0) {
        atomicAdd(o_diff, s * (1.0f / (float)(NROW * DIM)));
        if (half == 0) atomicAdd(&o_cs[j], OMDF);
    }
}

// ================= n = sum(new_cluster_size) =================
__global__ void k_sumn(const float* __restrict__ o_cs) {
    __shared__ float sh[256];
    float s = 0.0f;
    for (int i = threadIdx.x; i < NEMB; i += 256) s += o_cs[i];
    sh[threadIdx.x] = s;
    __syncthreads();
    for (int o = 128; o; o >>= 1) {
        if (threadIdx.x < o) sh[threadIdx.x] += sh[threadIdx.x + o];
        __syncthreads();
    }
    if (threadIdx.x == 0) g_n = sh[0];
}

// ================= new_embedding_avg + new_embedding =================
__global__ void k_final(const float* __restrict__ avg, const float* __restrict__ o_cs,
                        float* __restrict__ o_emb, float* __restrict__ o_avg) {
    int i = blockIdx.x * blockDim.x + threadIdx.x;
    if (i >= NEMB * DIM) return;
    int d = i >> 13;
    int j = i & (NEMB - 1);
    float na = fmaf(OMDF, g_esum[j * DIM + d], DECAYF * avg[i]);
    o_avg[i] = na;
    float n = g_n;
    float cs = o_cs[j];
    float smth = (cs + EPSF) / (n + (float)NEMB * EPSF) * n;
    o_emb[i] = na / smth;
}

extern "C" void kernel_launch(void* const* d_in, const int* in_sizes, int n_in,
                              void* d_out, int out_size) {
    (void)in_sizes; (void)n_in; (void)out_size;
    const float* z   = (const float*)d_in[0];
    const float* emb = (const float*)d_in[1];
    const float* cs  = (const float*)d_in[2];
    const float* avg = (const float*)d_in[3];

    float* out     = (float*)d_out;
    float* o_quant = out;                 // 4194304
    float* o_diff  = out + 4194304;       // 1
    float* o_ind   = out + 4194305;       // 16384
    float* o_emb   = out + 4210689;       // 2097152
    float* o_cs    = out + 6307841;       // 8192
    float* o_avg   = out + 6316033;       // 2097152

    cudaFuncSetAttribute(k_argmin_mma, cudaFuncAttributeMaxDynamicSharedMemorySize, SMEM_SZ);

    k_prep_z<<<(NROW * DIM + 255) / 256, 256>>>(z);
    {
        dim3 g(NEMB / 32, DIM / 32), b(32, 8);
        k_prep_e<<<g, b>>>(emb);
    }
    k_enorm<<<(NEMB + 255) / 256, 256>>>(emb, cs, o_cs, o_diff);
    k_argmin_mma<<<NROW / 128, 256, SMEM_SZ>>>(o_ind);
    k_scatter<<<(NROW * 64) / 256, 256>>>(z, o_quant, o_diff, o_cs);
    k_sumn<<<1, 256>>>(o_cs);
    k_final<<<(NEMB * DIM + 255) / 256, 256>>>(avg, o_cs, o_emb, o_avg);
}

// round 5
// speedup vs baseline: 6.0950x; 1.0911x over previous
#include <cuda_runtime.h>
#include <cuda_fp16.h>
#include <cstdint>

#define DIM    256
#define NEMB   8192
#define NROW   16384
#define DECAYF 0.99f
#define OMDF   0.01f
#define EPSF   1e-5f

// A: 2 regions (hi,lo) x 128 rows x 512B (256 fp16), padded stride 528B
#define AST    528
#define AREG   (128 * AST)          // 67584
#define BST    144                  // B slice row: 64 fp16 = 128B + 16 pad
#define BBUF   (128 * BST)          // 18432
#define SM_A   0
#define SM_B   (2 * AREG)           // 135168
#define SMEM_SZ (SM_B + 3 * BBUF)   // 190464
#define NSTG   512                  // 64 chunks x 8 stages

// ---- scratch (device globals: no allocations allowed) ----
__device__ float g_enorm[NEMB];
__device__ float g_embT[NEMB * DIM];          // [j][d] for coalesced gather
__device__ float g_esum[NEMB * DIM];          // [j][d] segment sums
__device__ int   g_argmin[NROW];
__device__ float g_n;
__device__ __half g_zs2[(size_t)NROW * 512];  // [m][hi(256)|lo(256)]
__device__ __half g_es2[(size_t)NEMB * 512];  // [j][hi(256)|lo(256)]

// ================= helpers =================
__device__ __forceinline__ uint32_t smem_u32(const void* p) {
    uint32_t a;
    asm("{ .reg .u64 t; cvta.to.shared.u64 t, %1; cvt.u32.u64 %0, t; }" : "=r"(a) : "l"(p));
    return a;
}
__device__ __forceinline__ void cpa16(uint32_t dst, const void* src) {
    asm volatile("cp.async.cg.shared.global [%0], [%1], 16;" :: "r"(dst), "l"(src));
}
__device__ __forceinline__ void ldm4(uint32_t (&r)[4], uint32_t addr) {
    asm volatile("ldmatrix.sync.aligned.m8n8.x4.shared.b16 {%0,%1,%2,%3}, [%4];"
                 : "=r"(r[0]), "=r"(r[1]), "=r"(r[2]), "=r"(r[3]) : "r"(addr));
}
__device__ __forceinline__ void mma16816(float (&d)[4], const uint32_t (&a)[4],
                                         uint32_t b0, uint32_t b1) {
    asm volatile(
        "mma.sync.aligned.m16n8k16.row.col.f32.f16.f16.f32 "
        "{%0,%1,%2,%3},{%4,%5,%6,%7},{%8,%9},{%0,%1,%2,%3};"
        : "+f"(d[0]), "+f"(d[1]), "+f"(d[2]), "+f"(d[3])
        : "r"(a[0]), "r"(a[1]), "r"(a[2]), "r"(a[3]), "r"(b0), "r"(b1));
}

// ================= prep: z -> [hi|lo] fp16 =================
__global__ void k_prep_z(const float* __restrict__ z) {
    int i = blockIdx.x * blockDim.x + threadIdx.x;
    if (i >= NROW * DIM) return;
    int m = i >> 8, d = i & 255;
    float x = z[i];
    __half hi = __float2half(x);
    __half lo = __float2half(x - __half2float(hi));
    size_t b = ((size_t)m << 9) + d;
    g_zs2[b] = hi; g_zs2[b + 256] = lo;
}

// ================= prep: emb -> [hi|lo] fp16 + embT + esum=0 (tiled transpose) ====
__global__ void k_prep_e(const float* __restrict__ emb) {
    __shared__ float t[32][33];
    int j0 = blockIdx.x * 32, d0 = blockIdx.y * 32;
    for (int r = threadIdx.y; r < 32; r += 8)
        t[r][threadIdx.x] = emb[(size_t)(d0 + r) * NEMB + j0 + threadIdx.x];
    __syncthreads();
    for (int r = threadIdx.y; r < 32; r += 8) {
        int j = j0 + r, d = d0 + threadIdx.x;
        float x = t[threadIdx.x][r];
        __half hi = __float2half(x);
        __half lo = __float2half(x - __half2float(hi));
        size_t b = ((size_t)j << 9) + d;
        g_es2[b] = hi; g_es2[b + 256] = lo;
        g_embT[j * DIM + d] = x;
        g_esum[j * DIM + d] = 0.0f;
    }
}

// ================= code norms + init cs + zero diff =================
__global__ void k_enorm(const float* __restrict__ emb, const float* __restrict__ cs,
                        float* __restrict__ o_cs, float* __restrict__ o_diff) {
    int j = blockIdx.x * blockDim.x + threadIdx.x;
    if (j < NEMB) {
        float s = 0.0f;
#pragma unroll 8
        for (int d = 0; d < DIM; ++d) {
            float v = emb[(size_t)d * NEMB + j];
            s = fmaf(v, v, s);
        }
        g_enorm[j] = s;
        o_cs[j] = DECAYF * cs[j];
        if (j == 0) *o_diff = 0.0f;
    }
}

// ================= main: HMMA fp16 3-term GEMM + argmin =================
__device__ __forceinline__ void load_B(int t, int slot, int tid, uint32_t sb) {
    const int ch = t >> 3;
    const int s = t & 7;
    const int n0 = ch << 7;
    const int scol = s << 6;            // 64 fp16 per stage; s<4 hi, s>=4 lo
    const char* ea = (const char*)g_es2;
#pragma unroll
    for (int r = 0; r < 2; ++r) {
        int i = tid + (r << 9);
        int c = i & 7, row = i >> 3;
        cpa16(sb + SM_B + slot * BBUF + row * BST + c * 16,
              ea + (((size_t)(n0 + row) << 9) + scol) * 2 + c * 16);
    }
}

__global__ __launch_bounds__(512, 1)
void k_argmin_mma(float* __restrict__ o_ind) {
    extern __shared__ char smm[];
    uint32_t sb = smem_u32(smm);
    const int tid = threadIdx.x;
    const int lane = tid & 31;
    const int warp = tid >> 5;
    const int warpM = warp >> 2;        // 0..3 (32 rows each)
    const int warpN = warp & 3;         // 0..3 (32 codes each)
    const int m0 = blockIdx.x * 128;

    // per-lane ldmatrix offsets
    const int q = lane >> 3, rq = lane & 7;
    const int lrow = (q & 1) * 8 + rq;
    const int lbyte = (q >> 1) * 16;
    const uint32_t a_lane = (uint32_t)lrow * AST + lbyte;
    const uint32_t b_lane = (uint32_t)lrow * BST + lbyte;

    // prologue: A (both regions) + stage 0 -> group0; stage 1 -> group1
    const char* za = (const char*)g_zs2;
#pragma unroll
    for (int r = 0; r < 16; ++r) {
        int i = tid + (r << 9);
        int c = i & 31, row = (i >> 5) & 127, reg = i >> 12;
        cpa16(sb + SM_A + reg * AREG + row * AST + c * 16,
              za + (((size_t)(m0 + row) << 9) + (reg << 8)) * 2 + c * 16);
    }
    load_B(0, 0, tid, sb);
    asm volatile("cp.async.commit_group;" ::: "memory");
    load_B(1, 1, tid, sb);
    asm volatile("cp.async.commit_group;" ::: "memory");

    float bestv[4];
    int   besti[4];
#pragma unroll
    for (int sl = 0; sl < 4; ++sl) { bestv[sl] = 3.4e38f; besti[sl] = 0; }

    const int lq = lane >> 2;
    const int ln = (lane & 3) * 2;

    float acc[2][4][4];
    int cur = 0, nxt = 2;

    for (int t = 0; t < NSTG; ++t) {
        const int s = t & 7;
        if (s == 0) {
#pragma unroll
            for (int mt = 0; mt < 2; ++mt)
#pragma unroll
                for (int nt = 0; nt < 4; ++nt)
#pragma unroll
                    for (int x = 0; x < 4; ++x) acc[mt][nt][x] = 0.0f;
        }

        if (t == NSTG - 1) {
            asm volatile("cp.async.wait_group 0;" ::: "memory");
        } else {
            asm volatile("cp.async.wait_group 1;" ::: "memory");
        }
        __syncthreads();     // stage t ready for all; mma(t-1) done by all

        if (t + 2 < NSTG) {
            load_B(t + 2, nxt, tid, sb);
            asm volatile("cp.async.commit_group;" ::: "memory");
        }

        const uint32_t Bb = sb + SM_B + cur * BBUF + (warpN * 32) * BST + b_lane;
        const uint32_t Ab0 = sb + SM_A + (warpM * 32) * AST + (s & 3) * 128 + a_lane;
        const bool two = (s < 4);
#pragma unroll
        for (int kk = 0; kk < 4; ++kk) {
            uint32_t b[2][4];
#pragma unroll
            for (int g = 0; g < 2; ++g)
                ldm4(b[g], Bb + g * 16 * BST + kk * 32);
            uint32_t a0[4], a1[4];
            ldm4(a0, Ab0 + kk * 32);
            ldm4(a1, Ab0 + 16 * AST + kk * 32);
#pragma unroll
            for (int nt = 0; nt < 4; ++nt) {
                uint32_t b0 = b[nt >> 1][nt & 1];
                uint32_t b1 = b[nt >> 1][(nt & 1) + 2];
                mma16816(acc[0][nt], a0, b0, b1);
                mma16816(acc[1][nt], a1, b0, b1);
            }
            if (two) {   // B-hi also pairs with A-lo region
                ldm4(a0, Ab0 + AREG + kk * 32);
                ldm4(a1, Ab0 + AREG + 16 * AST + kk * 32);
#pragma unroll
                for (int nt = 0; nt < 4; ++nt) {
                    uint32_t b0 = b[nt >> 1][nt & 1];
                    uint32_t b1 = b[nt >> 1][(nt & 1) + 2];
                    mma16816(acc[0][nt], a0, b0, b1);
                    mma16816(acc[1][nt], a1, b0, b1);
                }
            }
        }

        if (s == 7) {   // chunk done: fold into running argmin
            const int n0 = (t >> 3) << 7;
#pragma unroll
            for (int nt = 0; nt < 4; ++nt) {
                const int codeb = n0 + warpN * 32 + nt * 8 + ln;
#pragma unroll
                for (int jj = 0; jj < 2; ++jj) {
                    const int code = codeb + jj;
                    const float en = __ldg(&g_enorm[code]);
                    float d0 = fmaf(-2.0f, acc[0][nt][jj], en);
                    if (d0 < bestv[0]) { bestv[0] = d0; besti[0] = code; }
                    float d1 = fmaf(-2.0f, acc[0][nt][2 + jj], en);
                    if (d1 < bestv[1]) { bestv[1] = d1; besti[1] = code; }
                    float d2 = fmaf(-2.0f, acc[1][nt][jj], en);
                    if (d2 < bestv[2]) { bestv[2] = d2; besti[2] = code; }
                    float d3 = fmaf(-2.0f, acc[1][nt][2 + jj], en);
                    if (d3 < bestv[3]) { bestv[3] = d3; besti[3] = code; }
                }
            }
        }

        cur = (cur == 2) ? 0 : cur + 1;
        nxt = (nxt == 2) ? 0 : nxt + 1;
    }

    // final cross-thread reduction: 16 contributors per row
    __syncthreads();
    float* redv = (float*)(smm + SM_B);
    int*   redi = (int*)(smm + SM_B + 8192);
    const int contrib = warpN * 4 + (lane & 3);
#pragma unroll
    for (int sl = 0; sl < 4; ++sl) {
        int row = warpM * 32 + (sl >> 1) * 16 + (sl & 1) * 8 + lq;
        redv[row * 16 + contrib] = bestv[sl];
        redi[row * 16 + contrib] = besti[sl];
    }
    __syncthreads();
    if (tid < 128) {
        float bv = redv[tid * 16];
        int bi = redi[tid * 16];
#pragma unroll
        for (int t = 1; t < 16; ++t) {
            float v = redv[tid * 16 + t];
            int ix = redi[tid * 16 + t];
            if (v < bv || (v == bv && ix < bi)) { bv = v; bi = ix; }
        }
        g_argmin[m0 + tid] = bi;
        o_ind[m0 + tid] = (float)bi;
    }
}

// ================= gather quantize + diff + segment-sum scatter =================
// 2 warps per row (half a row each) for latency hiding
__global__ void k_scatter(const float* __restrict__ z, float* __restrict__ o_quant,
                          float* __restrict__ o_diff, float* __restrict__ o_cs) {
    int gw = (blockIdx.x * blockDim.x + threadIdx.x) >> 5;
    int lane = threadIdx.x & 31;
    int row = gw >> 1;
    int half = gw & 1;
    if (row >= NROW) return;
    int j = g_argmin[row];
    int dbase = half * 128;
    const float* et = &g_embT[(size_t)j * DIM + dbase];
    const float* zr = &z[(size_t)row * DIM + dbase];
    float* qr = &o_quant[(size_t)row * DIM + dbase];
    float* es = &g_esum[(size_t)j * DIM + dbase];
    float s = 0.0f;
#pragma unroll
    for (int it = 0; it < 4; ++it) {
        int d = it * 32 + lane;
        float qv = __ldg(&et[d]);
        float zv = zr[d];
        float dq = qv - zv;
        qr[d] = zv + dq;
        s = fmaf(dq, dq, s);
        atomicAdd(&es[d], zv);
    }
#pragma unroll
    for (int o = 16; o; o >>= 1) s += __shfl_xor_sync(0xffffffffu, s, o);
    if (lane == 0) {
        atomicAdd(o_diff, s * (1.0f / (float)(NROW * DIM)));
        if (half == 0) atomicAdd(&o_cs[j], OMDF);
    }
}

// ================= n = sum(new_cluster_size) =================
__global__ void k_sumn(const float* __restrict__ o_cs) {
    __shared__ float sh[256];
    float s = 0.0f;
    for (int i = threadIdx.x; i < NEMB; i += 256) s += o_cs[i];
    sh[threadIdx.x] = s;
    __syncthreads();
    for (int o = 128; o; o >>= 1) {
        if (threadIdx.x < o) sh[threadIdx.x] += sh[threadIdx.x + o];
        __syncthreads();
    }
    if (threadIdx.x == 0) g_n = sh[0];
}

// ================= new_embedding_avg + new_embedding =================
__global__ void k_final(const float* __restrict__ avg, const float* __restrict__ o_cs,
                        float* __restrict__ o_emb, float* __restrict__ o_avg) {
    int i = blockIdx.x * blockDim.x + threadIdx.x;
    if (i >= NEMB * DIM) return;
    int d = i >> 13;
    int j = i & (NEMB - 1);
    float na = fmaf(OMDF, g_esum[j * DIM + d], DECAYF * avg[i]);
    o_avg[i] = na;
    float n = g_n;
    float cs = o_cs[j];
    float smth = (cs + EPSF) / (n + (float)NEMB * EPSF) * n;
    o_emb[i] = na / smth;
}

extern "C" void kernel_launch(void* const* d_in, const int* in_sizes, int n_in,
                              void* d_out, int out_size) {
    (void)in_sizes; (void)n_in; (void)out_size;
    const float* z   = (const float*)d_in[0];
    const float* emb = (const float*)d_in[1];
    const float* cs  = (const float*)d_in[2];
    const float* avg = (const float*)d_in[3];

    float* out     = (float*)d_out;
    float* o_quant = out;                 // 4194304
    float* o_diff  = out + 4194304;       // 1
    float* o_ind   = out + 4194305;       // 16384
    float* o_emb   = out + 4210689;       // 2097152
    float* o_cs    = out + 6307841;       // 8192
    float* o_avg   = out + 6316033;       // 2097152

    cudaFuncSetAttribute(k_argmin_mma, cudaFuncAttributeMaxDynamicSharedMemorySize, SMEM_SZ);

    k_prep_z<<<(NROW * DIM + 255) / 256, 256>>>(z);
    {
        dim3 g(NEMB / 32, DIM / 32), b(32, 8);
        k_prep_e<<<g, b>>>(emb);
    }
    k_enorm<<<(NEMB + 255) / 256, 256>>>(emb, cs, o_cs, o_diff);
    k_argmin_mma<<<NROW / 128, 512, SMEM_SZ>>>(o_ind);
    k_scatter<<<(NROW * 64) / 256, 256>>>(z, o_quant, o_diff, o_cs);
    k_sumn<<<1, 256>>>(o_cs);
    k_final<<<(NEMB * DIM + 255) / 256, 256>>>(avg, o_cs, o_emb, o_avg);
}